// round 1
// baseline (speedup 1.0000x reference)
#include <cuda_runtime.h>
#include <math.h>

#define KK      3
#define ALPHA   8.3f
#define C_IN    64
#define C_OUT   64
#define H_IN    256
#define W_IN    256
#define H_OUT   254
#define W_OUT   254

#define TQ      32      // output tile width  (q)
#define TP      4       // output tile height (p)
#define CCH     8       // input-channel chunk per smem stage
#define NTHREADS 256

// Weight transposed to [c][k*3+l][o] so main-kernel loads are fully coalesced
// and smem reads are warp-broadcast LDS.128.
__device__ float g_wt[C_IN * 9 * C_OUT];

__global__ void transpose_w_kernel(const float* __restrict__ w) {
    int idx = blockIdx.x * blockDim.x + threadIdx.x;
    if (idx < C_IN * 9 * C_OUT) {
        int c  = idx / (9 * C_OUT);
        int kl = (idx / C_OUT) % 9;
        int o  = idx % C_OUT;
        g_wt[idx] = w[(o * C_IN + c) * 9 + kl];
    }
}

__global__ __launch_bounds__(NTHREADS, 2)
void depthconv_kernel(const float* __restrict__ img,
                      const float* __restrict__ depth,
                      const float* __restrict__ bias,
                      float* __restrict__ out) {
    __shared__ float s_img[CCH][TP + 2][TQ + 2];   // 8*6*34*4  = 6528 B
    __shared__ float s_w[CCH * 9 * C_OUT];         // 4608*4    = 18432 B
    __shared__ float s_dw[9][TP][TQ];              // 1152*4    = 4608 B
    __shared__ float s_d[TP + 2][TQ + 2];          // 204*4     = 816 B
    __shared__ float s_b[C_OUT];                   // 256 B

    const int tid = threadIdx.x;
    const int qt  = tid & 31;     // lane -> q offset within tile
    const int og  = tid >> 5;     // warp -> oc group (8 OC each)
    const int q0  = blockIdx.x * TQ;
    const int p0  = blockIdx.y * TP;
    const int b   = blockIdx.z;

    // ---- stage depth patch ----
    const float* dp = depth + (size_t)b * H_IN * W_IN;
    for (int idx = tid; idx < (TP + 2) * (TQ + 2); idx += NTHREADS) {
        int r = idx / (TQ + 2);
        int c = idx - r * (TQ + 2);
        int gp = min(p0 + r, H_IN - 1);
        int gq = min(q0 + c, W_IN - 1);
        s_d[r][c] = dp[gp * W_IN + gq];
    }
    if (tid < C_OUT) s_b[tid] = bias[tid];
    __syncthreads();

    // ---- precompute depth weights dw[k,l,p,q] (channel-independent) ----
    for (int idx = tid; idx < 9 * TP * TQ; idx += NTHREADS) {
        int kl = idx / (TP * TQ);
        int k  = kl / 3;
        int l  = kl - k * 3;
        int r  = (idx / TQ) % TP;
        int qq = idx & (TQ - 1);
        float cen = s_d[r + 1][qq + 1];
        s_dw[kl][r][qq] = __expf(-ALPHA * fabsf(s_d[r + k][qq + l] - cen));
    }
    // (visibility of s_dw covered by the __syncthreads at top of the cc loop)

    float acc[8][TP];
#pragma unroll
    for (int i = 0; i < 8; i++)
#pragma unroll
        for (int j = 0; j < TP; j++) acc[i][j] = 0.f;

    // ---- main loop over input-channel chunks ----
    for (int cc = 0; cc < C_IN; cc += CCH) {
        __syncthreads();  // protect smem reuse (and first-iter s_dw visibility)

        const float* ip = img + ((size_t)(b * C_IN + cc)) * H_IN * W_IN;
        for (int idx = tid; idx < CCH * (TP + 2) * (TQ + 2); idx += NTHREADS) {
            int c   = idx / ((TP + 2) * (TQ + 2));
            int rem = idx - c * ((TP + 2) * (TQ + 2));
            int r   = rem / (TQ + 2);
            int col = rem - r * (TQ + 2);
            int gp  = min(p0 + r, H_IN - 1);
            int gq  = min(q0 + col, W_IN - 1);
            s_img[c][r][col] = ip[((size_t)c * H_IN + gp) * W_IN + gq];
        }
        const float* wp = g_wt + (size_t)cc * 9 * C_OUT;
        for (int idx = tid; idx < CCH * 9 * C_OUT; idx += NTHREADS) {
            s_w[idx] = wp[idx];   // fully coalesced, linear smem store
        }
        __syncthreads();

#pragma unroll
        for (int k = 0; k < 3; k++) {
#pragma unroll
            for (int l = 0; l < 3; l++) {
                const int kl = k * 3 + l;
                float dwv[TP];
#pragma unroll
                for (int j = 0; j < TP; j++) dwv[j] = s_dw[kl][j][qt];
#pragma unroll
                for (int c = 0; c < CCH; c++) {
                    float xv[TP];
#pragma unroll
                    for (int j = 0; j < TP; j++)
                        xv[j] = s_img[c][j + k][qt + l] * dwv[j];

                    // warp-broadcast weight loads (all lanes in a warp share og)
                    const float4* w4 = reinterpret_cast<const float4*>(
                        &s_w[(c * 9 + kl) * C_OUT + og * 8]);
                    float4 wa = w4[0];
                    float4 wb = w4[1];
                    float wr[8] = {wa.x, wa.y, wa.z, wa.w,
                                   wb.x, wb.y, wb.z, wb.w};
#pragma unroll
                    for (int i = 0; i < 8; i++)
#pragma unroll
                        for (int j = 0; j < TP; j++)
                            acc[i][j] = fmaf(wr[i], xv[j], acc[i][j]);
                }
            }
        }
    }

    // ---- store ----
    const int q = q0 + qt;
    if (q < W_OUT) {
#pragma unroll
        for (int j = 0; j < TP; j++) {
            int p = p0 + j;
            if (p < H_OUT) {
#pragma unroll
                for (int i = 0; i < 8; i++) {
                    int o = og * 8 + i;
                    out[(((size_t)b * C_OUT + o) * H_OUT + p) * W_OUT + q] =
                        acc[i][j] + s_b[o];
                }
            }
        }
    }
}

extern "C" void kernel_launch(void* const* d_in, const int* in_sizes, int n_in,
                              void* d_out, int out_size) {
    const float* img    = nullptr;
    const float* depth  = nullptr;
    const float* weight = nullptr;
    const float* bias   = nullptr;

    // Identify inputs by element count (robust to metadata ordering).
    for (int i = 0; i < n_in; i++) {
        switch (in_sizes[i]) {
            case 4 * C_IN * H_IN * W_IN:  img    = (const float*)d_in[i]; break; // 16777216
            case 4 * 1 * H_IN * W_IN:     depth  = (const float*)d_in[i]; break; // 262144
            case C_OUT * C_IN * KK * KK:  weight = (const float*)d_in[i]; break; // 36864
            case C_OUT:                   bias   = (const float*)d_in[i]; break; // 64
            default: break;
        }
    }

    transpose_w_kernel<<<(C_IN * 9 * C_OUT + 255) / 256, 256>>>(weight);

    dim3 grid((W_OUT + TQ - 1) / TQ,   // 8
              (H_OUT + TP - 1) / TP,   // 64
              4);                      // batch
    depthconv_kernel<<<grid, NTHREADS>>>(img, depth, bias, (float*)d_out);
}

// round 2
// speedup vs baseline: 1.2347x; 1.2347x over previous
#include <cuda_runtime.h>
#include <math.h>

#define KK      3
#define ALPHA   8.3f
#define C_IN    64
#define C_OUT   64
#define H_IN    256
#define W_IN    256
#define H_OUT   254
#define W_OUT   254

#define TQ      32      // output tile width  (q)
#define TP      4       // output tile height (p)
#define CCH     8       // input-channel chunk per smem stage
#define NTHREADS 256

typedef unsigned long long u64;

// ---- packed fp32x2 helpers (Blackwell FFMA2 path, PTX-only) ----
__device__ __forceinline__ u64 pack2(float lo, float hi) {
    u64 r;
    asm("mov.b64 %0, {%1, %2};" : "=l"(r) : "f"(lo), "f"(hi));
    return r;
}
__device__ __forceinline__ void unpack2(u64 v, float& lo, float& hi) {
    asm("mov.b64 {%0, %1}, %2;" : "=f"(lo), "=f"(hi) : "l"(v));
}
__device__ __forceinline__ u64 fma2(u64 a, u64 b, u64 c) {
    u64 d;
    asm("fma.rn.f32x2 %0, %1, %2, %3;" : "=l"(d) : "l"(a), "l"(b), "l"(c));
    return d;
}

// Weight transposed to [c][k*3+l][o]: main-kernel smem reads are warp-broadcast
// LDS.128 yielding naturally packed (oc even, oc odd) f32x2 pairs.
__device__ float g_wt[C_IN * 9 * C_OUT];

__global__ void transpose_w_kernel(const float* __restrict__ w) {
    int idx = blockIdx.x * blockDim.x + threadIdx.x;
    if (idx < C_IN * 9 * C_OUT) {
        int c  = idx / (9 * C_OUT);
        int kl = (idx / C_OUT) % 9;
        int o  = idx % C_OUT;
        g_wt[idx] = w[(o * C_IN + c) * 9 + kl];
    }
}

__global__ __launch_bounds__(NTHREADS, 2)
void depthconv_kernel(const float* __restrict__ img,
                      const float* __restrict__ depth,
                      const float* __restrict__ bias,
                      float* __restrict__ out) {
    __shared__ float s_img[CCH][TP + 2][TQ + 2];   // 6528 B
    __shared__ float s_w[CCH * 9 * C_OUT];         // 18432 B
    __shared__ float s_dw[9][TP][TQ];              // 4608 B
    __shared__ float s_d[TP + 2][TQ + 2];          // 816 B
    __shared__ float s_b[C_OUT];                   // 256 B

    const int tid = threadIdx.x;
    const int qt  = tid & 31;     // lane -> q offset within tile
    const int og  = tid >> 5;     // warp -> oc group (8 OC each)
    const int q0  = blockIdx.x * TQ;
    const int p0  = blockIdx.y * TP;
    const int b   = blockIdx.z;

    // ---- stage depth patch ----
    const float* dp = depth + (size_t)b * H_IN * W_IN;
    for (int idx = tid; idx < (TP + 2) * (TQ + 2); idx += NTHREADS) {
        int r = idx / (TQ + 2);
        int c = idx - r * (TQ + 2);
        int gp = min(p0 + r, H_IN - 1);
        int gq = min(q0 + c, W_IN - 1);
        s_d[r][c] = dp[gp * W_IN + gq];
    }
    if (tid < C_OUT) s_b[tid] = bias[tid];
    __syncthreads();

    // ---- precompute depth weights dw[k,l,p,q] (channel-independent) ----
    for (int idx = tid; idx < 9 * TP * TQ; idx += NTHREADS) {
        int kl = idx / (TP * TQ);
        int k  = kl / 3;
        int l  = kl - k * 3;
        int r  = (idx / TQ) % TP;
        int qq = idx & (TQ - 1);
        float cen = s_d[r + 1][qq + 1];
        s_dw[kl][r][qq] = __expf(-ALPHA * fabsf(s_d[r + k][qq + l] - cen));
    }
    __syncthreads();

    // hoist c-invariant dw into registers (36 regs)
    float dwreg[9][TP];
#pragma unroll
    for (int kl = 0; kl < 9; kl++)
#pragma unroll
        for (int j = 0; j < TP; j++)
            dwreg[kl][j] = s_dw[kl][j][qt];

    // accumulators: pair over adjacent OC; acc2[i][j] holds oc {og*8+2i, og*8+2i+1}, p=j
    u64 acc2[4][TP];
#pragma unroll
    for (int i = 0; i < 4; i++)
#pragma unroll
        for (int j = 0; j < TP; j++) acc2[i][j] = 0ull;

    // ---- main loop over input-channel chunks ----
    for (int cc = 0; cc < C_IN; cc += CCH) {
        __syncthreads();  // protect smem reuse

        const float* ip = img + ((size_t)(b * C_IN + cc)) * H_IN * W_IN;
        for (int idx = tid; idx < CCH * (TP + 2) * (TQ + 2); idx += NTHREADS) {
            int c   = idx / ((TP + 2) * (TQ + 2));
            int rem = idx - c * ((TP + 2) * (TQ + 2));
            int r   = rem / (TQ + 2);
            int col = rem - r * (TQ + 2);
            int gp  = min(p0 + r, H_IN - 1);
            int gq  = min(q0 + col, W_IN - 1);
            s_img[c][r][col] = ip[((size_t)c * H_IN + gp) * W_IN + gq];
        }
        const float* wp = g_wt + (size_t)cc * 9 * C_OUT;
        for (int idx = tid; idx < CCH * 9 * C_OUT; idx += NTHREADS) {
            s_w[idx] = wp[idx];   // coalesced, linear smem store
        }
        __syncthreads();

#pragma unroll
        for (int c = 0; c < CCH; c++) {
#pragma unroll
            for (int l = 0; l < 3; l++) {
                // one column of the img patch: rows 0..5 at q = qt+l
                float x[6];
#pragma unroll
                for (int r = 0; r < 6; r++) x[r] = s_img[c][r][qt + l];

#pragma unroll
                for (int k = 0; k < 3; k++) {
                    const int kl = k * 3 + l;
                    // xv = img * dw, duplicated into both f32x2 lanes
                    u64 xv2[TP];
#pragma unroll
                    for (int j = 0; j < TP; j++) {
                        float v = x[j + k] * dwreg[kl][j];
                        xv2[j] = pack2(v, v);
                    }
                    // weights: two LDS.128 -> 4 naturally-packed oc pairs
                    const ulonglong2* w2p = reinterpret_cast<const ulonglong2*>(
                        &s_w[(c * 9 + kl) * C_OUT + og * 8]);
                    ulonglong2 wA = w2p[0];
                    ulonglong2 wB = w2p[1];
                    u64 w2[4] = {wA.x, wA.y, wB.x, wB.y};
#pragma unroll
                    for (int i = 0; i < 4; i++)
#pragma unroll
                        for (int j = 0; j < TP; j++)
                            acc2[i][j] = fma2(w2[i], xv2[j], acc2[i][j]);
                }
            }
        }
    }

    // ---- store ----
    const int q = q0 + qt;
    if (q < W_OUT) {
#pragma unroll
        for (int j = 0; j < TP; j++) {
            int p = p0 + j;
            if (p < H_OUT) {
#pragma unroll
                for (int i = 0; i < 4; i++) {
                    float lo, hi;
                    unpack2(acc2[i][j], lo, hi);
                    int o = og * 8 + 2 * i;
                    size_t base = (((size_t)b * C_OUT + o) * H_OUT + p) * W_OUT + q;
                    out[base] = lo + s_b[o];
                    out[base + (size_t)H_OUT * W_OUT] = hi + s_b[o + 1];
                }
            }
        }
    }
}

extern "C" void kernel_launch(void* const* d_in, const int* in_sizes, int n_in,
                              void* d_out, int out_size) {
    const float* img    = nullptr;
    const float* depth  = nullptr;
    const float* weight = nullptr;
    const float* bias   = nullptr;

    for (int i = 0; i < n_in; i++) {
        switch (in_sizes[i]) {
            case 4 * C_IN * H_IN * W_IN:  img    = (const float*)d_in[i]; break;
            case 4 * 1 * H_IN * W_IN:     depth  = (const float*)d_in[i]; break;
            case C_OUT * C_IN * KK * KK:  weight = (const float*)d_in[i]; break;
            case C_OUT:                   bias   = (const float*)d_in[i]; break;
            default: break;
        }
    }

    transpose_w_kernel<<<(C_IN * 9 * C_OUT + 255) / 256, 256>>>(weight);

    dim3 grid((W_OUT + TQ - 1) / TQ,   // 8
              (H_OUT + TP - 1) / TP,   // 64
              4);                      // batch
    depthconv_kernel<<<grid, NTHREADS>>>(img, depth, bias, (float*)d_out);
}

// round 5
// speedup vs baseline: 3.3999x; 2.7536x over previous
#include <cuda_runtime.h>
#include <math.h>

typedef unsigned int u32;

#define ALPHA   8.3f
#define C_IN    64
#define C_OUT   64
#define H_IN    256
#define W_IN    256
#define H_OUT   254
#define W_OUT   254

#define NTHREADS 256
#define NCTAS    148
#define TILES_PER_BATCH (127 * 4)   // 127 p-pairs x 4 q-tiles of 64
#define NTILES   (4 * TILES_PER_BATCH)

// ---- smem layout (bytes) ----
#define OFF_BIAS 0                       // 64 f            = 256
#define OFF_D    256                     // 4 x 66 f        = 1056
#define OFF_DW   1312                    // 9 x 128 f       = 4608
#define OFF_W    5920                    // 72*8*32 float2  = 147456
#define OFF_IMG  153376                  // 64 x 264 f      = 67584
#define SMEM_TOTAL 220960

__device__ __forceinline__ u32 to_tf32(float x) {
    u32 u;
    asm("cvt.rn.tf32.f32 %0, %1;" : "=r"(u) : "f"(x));
    return u;
}

// mma.sync m16n8k8 tf32: D(16x8,f32) += A(16x8,tf32) * B(8x8,tf32)
#define MMA_TF32(d, a, b0, b1)                                              \
    asm volatile(                                                           \
        "mma.sync.aligned.m16n8k8.row.col.f32.tf32.tf32.f32 "               \
        "{%0,%1,%2,%3}, {%4,%5,%6,%7}, {%8,%9}, {%0,%1,%2,%3};"             \
        : "+f"((d)[0]), "+f"((d)[1]), "+f"((d)[2]), "+f"((d)[3])            \
        : "r"((a)[0]), "r"((a)[1]), "r"((a)[2]), "r"((a)[3]),               \
          "r"(b0), "r"(b1))

// W pre-packed into B-fragment layout: [kc(72)][nbg(8)][lane(32)] float2.
// kc = kl*8 + cs; thread lane holds W'[oc = nbg*8 + (lane>>2)][c = cs*8 + (lane&3)]
// in .x and the same at c+4 in .y (k-rows t and t+4 of the 8x8 B block).
__device__ __align__(16) float2 g_wfrag[72 * 8 * 32];

__global__ void prep_w(const float* __restrict__ w) {
    int idx = blockIdx.x * blockDim.x + threadIdx.x;
    if (idx >= 72 * 8 * 32) return;
    int lane = idx & 31;
    int nbg  = (idx >> 5) & 7;
    int kc   = idx >> 8;
    int kl = kc >> 3, cs = kc & 7;
    int oc = nbg * 8 + (lane >> 2);
    int t  = lane & 3;
    int c0 = cs * 8 + t;
    float2 v;
    v.x = __uint_as_float(to_tf32(w[(oc * C_IN + c0)     * 9 + kl]));
    v.y = __uint_as_float(to_tf32(w[(oc * C_IN + c0 + 4) * 9 + kl]));
    g_wfrag[idx] = v;
}

__global__ __launch_bounds__(NTHREADS, 1)
void depthconv_mma(const float* __restrict__ img,
                   const float* __restrict__ depth,
                   const float* __restrict__ bias,
                   float* __restrict__ out) {
    extern __shared__ char smem[];
    float*  s_b   = (float*) (smem + OFF_BIAS);
    float*  s_d   = (float*) (smem + OFF_D);
    float*  s_dw  = (float*) (smem + OFF_DW);
    float2* s_w   = (float2*)(smem + OFF_W);
    float*  s_img = (float*) (smem + OFF_IMG);

    const int tid   = threadIdx.x;
    const int lane  = tid & 31;
    const int wid   = tid >> 5;
    const int g     = lane >> 2;         // groupID
    const int t     = lane & 3;          // threadID_in_group
    const int warpM = wid & 3;           // 4 warps along M (32 rows each)
    const int warpN = wid >> 2;          // 2 warps along N (32 oc each)
    const int pr    = warpM >> 1;        // output row within p-pair
    const int qb0   = (warpM & 1) * 32;  // q base of mb=0 m16 block

    // ---- load W fragments + bias once (persistent) ----
    {
        const float4* src = (const float4*)g_wfrag;
        float4* dst = (float4*)(smem + OFF_W);
        for (int i = tid; i < 9216; i += NTHREADS) dst[i] = src[i];
        if (tid < C_OUT) s_b[tid] = bias[tid];
    }
    __syncthreads();

    for (int tIdx = blockIdx.x; tIdx < NTILES; tIdx += NCTAS) {
        const int b  = tIdx / TILES_PER_BATCH;
        const int r  = tIdx - b * TILES_PER_BATCH;
        const int p0 = (r >> 2) << 1;    // 0..252 (rows p0..p0+3 all < 256)
        const int q0 = (r & 3) << 6;
        const int qcnt = min(64, W_OUT - q0);

        // ---- stage depth halo (4 x 66) ----
        for (int i = tid; i < 264; i += NTHREADS) {
            int rr = i / 66, cc = i - rr * 66;
            s_d[i] = depth[(size_t)b * H_IN * W_IN + (p0 + rr) * W_IN +
                           min(q0 + cc, W_IN - 1)];
        }
        // ---- stage img: 64 ch x 4 rows x 66 q (FIX: cover all 66 cols) ----
        {
            const float* ip = img + (size_t)b * C_IN * H_IN * W_IN;
            for (int c = wid; c < C_IN; c += 8) {
                const float* row0 = ip + ((size_t)c * H_IN + p0) * W_IN;
                float* sd = s_img + c * 264;
#pragma unroll
                for (int rr = 0; rr < 4; rr++) {
#pragma unroll
                    for (int cc = lane; cc < 66; cc += 32)
                        sd[rr * 66 + cc] = row0[rr * W_IN + min(q0 + cc, W_IN - 1)];
                }
            }
        }
        __syncthreads();
        // ---- dw[kl][m] (channel-independent) ----
        for (int i = tid; i < 1152; i += NTHREADS) {
            int kl = i >> 7, m = i & 127;
            int mpr = m >> 6, qq = m & 63;
            int k = kl / 3, l = kl - k * 3;
            float cen = s_d[(mpr + 1) * 66 + qq + 1];
            s_dw[i] = __expf(-ALPHA * fabsf(s_d[(mpr + k) * 66 + qq + l] - cen));
        }
        __syncthreads();

        float acc[2][4][4];
#pragma unroll
        for (int mb = 0; mb < 2; mb++)
#pragma unroll
            for (int nb = 0; nb < 4; nb++)
#pragma unroll
                for (int rr = 0; rr < 4; rr++) acc[mb][nb][rr] = 0.f;

        // ---- K loop: 9 kl x 8 channel-subchunks ----
#pragma unroll
        for (int kl = 0; kl < 9; kl++) {
            const int k = kl / 3, l = kl - k * 3;
            const float* dwp = s_dw + kl * 128 + pr * 64;
            const float dw00 = dwp[qb0 + g];
            const float dw01 = dwp[qb0 + g + 8];
            const float dw10 = dwp[qb0 + 16 + g];
            const float dw11 = dwp[qb0 + 16 + g + 8];
            const int ib = (pr + k) * 66 + l;

#pragma unroll
            for (int cs = 0; cs < 8; cs++) {
                const float* pc0 = s_img + (cs * 8 + t) * 264 + ib;   // channel c0
                const float* pc1 = pc0 + 4 * 264;                     // channel c0+4

                u32 A0[4], A1[4];
                A0[0] = to_tf32(pc0[qb0 + g]          * dw00);
                A0[1] = to_tf32(pc0[qb0 + g + 8]      * dw01);
                A0[2] = to_tf32(pc1[qb0 + g]          * dw00);
                A0[3] = to_tf32(pc1[qb0 + g + 8]      * dw01);
                A1[0] = to_tf32(pc0[qb0 + 16 + g]     * dw10);
                A1[1] = to_tf32(pc0[qb0 + 16 + g + 8] * dw11);
                A1[2] = to_tf32(pc1[qb0 + 16 + g]     * dw10);
                A1[3] = to_tf32(pc1[qb0 + 16 + g + 8] * dw11);

                const int kc = kl * 8 + cs;
                const float2* wf = s_w + (size_t)(kc * 8 + warpN * 4) * 32 + lane;
#pragma unroll
                for (int nb = 0; nb < 4; nb++) {
                    float2 bv = wf[nb * 32];
                    u32 b0 = __float_as_uint(bv.x);
                    u32 b1 = __float_as_uint(bv.y);
                    MMA_TF32(acc[0][nb], A0, b0, b1);
                    MMA_TF32(acc[1][nb], A1, b0, b1);
                }
            }
        }

        // ---- epilogue: bias + store ----
#pragma unroll
        for (int mb = 0; mb < 2; mb++) {
            const int qq0 = qb0 + mb * 16 + g;
#pragma unroll
            for (int nb = 0; nb < 4; nb++) {
                const int oc = warpN * 32 + nb * 8 + t * 2;
                const float bs0 = s_b[oc], bs1 = s_b[oc + 1];
                const size_t base =
                    (((size_t)b * C_OUT + oc) * H_OUT + (p0 + pr)) * W_OUT + q0;
                if (qq0 < qcnt) {
                    out[base + qq0]                          = acc[mb][nb][0] + bs0;
                    out[base + (size_t)H_OUT * W_OUT + qq0]  = acc[mb][nb][1] + bs1;
                }
                if (qq0 + 8 < qcnt) {
                    out[base + qq0 + 8]                         = acc[mb][nb][2] + bs0;
                    out[base + (size_t)H_OUT * W_OUT + qq0 + 8] = acc[mb][nb][3] + bs1;
                }
            }
        }
        __syncthreads();   // protect s_img/s_d/s_dw before next tile's staging
    }
}

extern "C" void kernel_launch(void* const* d_in, const int* in_sizes, int n_in,
                              void* d_out, int out_size) {
    const float* img    = nullptr;
    const float* depth  = nullptr;
    const float* weight = nullptr;
    const float* bias   = nullptr;

    for (int i = 0; i < n_in; i++) {
        switch (in_sizes[i]) {
            case 4 * C_IN * H_IN * W_IN: img    = (const float*)d_in[i]; break;
            case 4 * 1 * H_IN * W_IN:    depth  = (const float*)d_in[i]; break;
            case C_OUT * C_IN * 9:       weight = (const float*)d_in[i]; break;
            case C_OUT:                  bias   = (const float*)d_in[i]; break;
            default: break;
        }
    }

    cudaFuncSetAttribute(depthconv_mma,
                         cudaFuncAttributeMaxDynamicSharedMemorySize, SMEM_TOTAL);

    prep_w<<<(72 * 8 * 32 + 255) / 256, 256>>>(weight);
    depthconv_mma<<<NCTAS, NTHREADS, SMEM_TOTAL>>>(img, depth, bias, (float*)d_out);
}

// round 6
// speedup vs baseline: 4.3967x; 1.2932x over previous
#include <cuda_runtime.h>
#include <math.h>

typedef unsigned int u32;

#define ALPHA   8.3f
#define C_IN    64
#define C_OUT   64
#define H_IN    256
#define W_IN    256
#define H_OUT   254
#define W_OUT   254

#define NTHREADS 256
#define TILES_PER_BATCH (127 * 4)   // 127 p-pairs x 4 q-tiles of 64
#define NTILES   (4 * TILES_PER_BATCH)

// ---- smem layout (bytes) ----
#define OFF_BIAS 0                       // 64 f            = 256
#define OFF_D    256                     // 4 x 66 f        = 1056
#define OFF_DW   1312                    // 9 x 128 f       = 4608
#define OFF_IMG  5920                    // 64 x 264 f      = 67584
#define SMEM_TOTAL 73504

__device__ __forceinline__ u32 to_tf32(float x) {
    u32 u;
    asm("cvt.rn.tf32.f32 %0, %1;" : "=r"(u) : "f"(x));
    return u;
}

// mma.sync m16n8k8 tf32: D(16x8,f32) += A(16x8,tf32) * B(8x8,tf32)
#define MMA_TF32(d, a, b0, b1)                                              \
    asm volatile(                                                           \
        "mma.sync.aligned.m16n8k8.row.col.f32.tf32.tf32.f32 "               \
        "{%0,%1,%2,%3}, {%4,%5,%6,%7}, {%8,%9}, {%0,%1,%2,%3};"             \
        : "+f"((d)[0]), "+f"((d)[1]), "+f"((d)[2]), "+f"((d)[3])            \
        : "r"((a)[0]), "r"((a)[1]), "r"((a)[2]), "r"((a)[3]),               \
          "r"(b0), "r"(b1))

// W pre-packed into B-fragment layout: [kc(72)][nbg(8)][lane(32)] float2.
// kc = kl*8 + cs; thread lane holds W'[oc = nbg*8 + (lane>>2)][c = cs*8 + (lane&3)]
// in .x and the same at c+4 in .y (k-rows t and t+4 of the 8x8 B block).
__device__ __align__(16) float2 g_wfrag[72 * 8 * 32];

__global__ void prep_w(const float* __restrict__ w) {
    int idx = blockIdx.x * blockDim.x + threadIdx.x;
    if (idx >= 72 * 8 * 32) return;
    int lane = idx & 31;
    int nbg  = (idx >> 5) & 7;
    int kc   = idx >> 8;
    int kl = kc >> 3, cs = kc & 7;
    int oc = nbg * 8 + (lane >> 2);
    int t  = lane & 3;
    int c0 = cs * 8 + t;
    float2 v;
    v.x = __uint_as_float(to_tf32(w[(oc * C_IN + c0)     * 9 + kl]));
    v.y = __uint_as_float(to_tf32(w[(oc * C_IN + c0 + 4) * 9 + kl]));
    g_wfrag[idx] = v;
}

__global__ __launch_bounds__(NTHREADS, 2)
void depthconv_mma(const float* __restrict__ img,
                   const float* __restrict__ depth,
                   const float* __restrict__ bias,
                   float* __restrict__ out) {
    extern __shared__ char smem[];
    float*  s_b   = (float*) (smem + OFF_BIAS);
    float*  s_d   = (float*) (smem + OFF_D);
    float*  s_dw  = (float*) (smem + OFF_DW);
    float*  s_img = (float*) (smem + OFF_IMG);

    const int tid   = threadIdx.x;
    const int lane  = tid & 31;
    const int wid   = tid >> 5;
    const int g     = lane >> 2;         // groupID
    const int t     = lane & 3;          // threadID_in_group
    const int warpM = wid & 3;           // 4 warps along M (32 rows each)
    const int warpN = wid >> 2;          // 2 warps along N (32 oc each)
    const int pr    = warpM >> 1;        // output row within p-pair
    const int qb0   = (warpM & 1) * 32;  // q base of mb=0 m16 block

    const int tIdx = blockIdx.x;
    const int b  = tIdx / TILES_PER_BATCH;
    const int r  = tIdx - b * TILES_PER_BATCH;
    const int p0 = (r >> 2) << 1;    // 0..252
    const int q0 = (r & 3) << 6;
    const int qcnt = min(64, W_OUT - q0);

    // ---- stage bias + depth halo (4 x 66) ----
    if (tid < C_OUT) s_b[tid] = bias[tid];
    for (int i = tid; i < 264; i += NTHREADS) {
        int rr = i / 66, cc = i - rr * 66;
        s_d[i] = depth[(size_t)b * H_IN * W_IN + (p0 + rr) * W_IN +
                       min(q0 + cc, W_IN - 1)];
    }
    // ---- stage img: 64 ch x 4 rows x 66 q ----
    {
        const float* ip = img + (size_t)b * C_IN * H_IN * W_IN;
        for (int c = wid; c < C_IN; c += 8) {
            const float* row0 = ip + ((size_t)c * H_IN + p0) * W_IN;
            float* sd = s_img + c * 264;
#pragma unroll
            for (int rr = 0; rr < 4; rr++) {
#pragma unroll
                for (int cc = lane; cc < 66; cc += 32)
                    sd[rr * 66 + cc] = row0[rr * W_IN + min(q0 + cc, W_IN - 1)];
            }
        }
    }
    __syncthreads();
    // ---- dw[kl][m] (channel-independent) ----
    for (int i = tid; i < 1152; i += NTHREADS) {
        int kl = i >> 7, m = i & 127;
        int mpr = m >> 6, qq = m & 63;
        int k = kl / 3, l = kl - k * 3;
        float cen = s_d[(mpr + 1) * 66 + qq + 1];
        s_dw[i] = __expf(-ALPHA * fabsf(s_d[(mpr + k) * 66 + qq + l] - cen));
    }
    __syncthreads();

    float acc[2][4][4];
#pragma unroll
    for (int mb = 0; mb < 2; mb++)
#pragma unroll
        for (int nb = 0; nb < 4; nb++)
#pragma unroll
            for (int rr = 0; rr < 4; rr++) acc[mb][nb][rr] = 0.f;

    // ---- K loop: 9 kl x 8 channel-subchunks; W straight from global (L1/L2) ----
    const float2* wbase = g_wfrag + (size_t)warpN * 4 * 32 + lane;
#pragma unroll
    for (int kl = 0; kl < 9; kl++) {
        const int k = kl / 3, l = kl - k * 3;
        const float* dwp = s_dw + kl * 128 + pr * 64;
        const float dw00 = dwp[qb0 + g];
        const float dw01 = dwp[qb0 + g + 8];
        const float dw10 = dwp[qb0 + 16 + g];
        const float dw11 = dwp[qb0 + 16 + g + 8];
        const int ib = (pr + k) * 66 + l;

#pragma unroll
        for (int cs = 0; cs < 8; cs++) {
            const float* pc0 = s_img + (cs * 8 + t) * 264 + ib;   // channel c0
            const float* pc1 = pc0 + 4 * 264;                     // channel c0+4

            // issue W loads first (independent of LDS chain)
            const int kc = kl * 8 + cs;
            const float2* wf = wbase + (size_t)kc * 256;
            float2 bv0 = __ldg(wf);
            float2 bv1 = __ldg(wf + 32);
            float2 bv2 = __ldg(wf + 64);
            float2 bv3 = __ldg(wf + 96);

            u32 A0[4], A1[4];
            A0[0] = to_tf32(pc0[qb0 + g]          * dw00);
            A0[1] = to_tf32(pc0[qb0 + g + 8]      * dw01);
            A0[2] = to_tf32(pc1[qb0 + g]          * dw00);
            A0[3] = to_tf32(pc1[qb0 + g + 8]      * dw01);
            A1[0] = to_tf32(pc0[qb0 + 16 + g]     * dw10);
            A1[1] = to_tf32(pc0[qb0 + 16 + g + 8] * dw11);
            A1[2] = to_tf32(pc1[qb0 + 16 + g]     * dw10);
            A1[3] = to_tf32(pc1[qb0 + 16 + g + 8] * dw11);

            MMA_TF32(acc[0][0], A0, __float_as_uint(bv0.x), __float_as_uint(bv0.y));
            MMA_TF32(acc[1][0], A1, __float_as_uint(bv0.x), __float_as_uint(bv0.y));
            MMA_TF32(acc[0][1], A0, __float_as_uint(bv1.x), __float_as_uint(bv1.y));
            MMA_TF32(acc[1][1], A1, __float_as_uint(bv1.x), __float_as_uint(bv1.y));
            MMA_TF32(acc[0][2], A0, __float_as_uint(bv2.x), __float_as_uint(bv2.y));
            MMA_TF32(acc[1][2], A1, __float_as_uint(bv2.x), __float_as_uint(bv2.y));
            MMA_TF32(acc[0][3], A0, __float_as_uint(bv3.x), __float_as_uint(bv3.y));
            MMA_TF32(acc[1][3], A1, __float_as_uint(bv3.x), __float_as_uint(bv3.y));
        }
    }

    // ---- epilogue: bias + store ----
#pragma unroll
    for (int mb = 0; mb < 2; mb++) {
        const int qq0 = qb0 + mb * 16 + g;
#pragma unroll
        for (int nb = 0; nb < 4; nb++) {
            const int oc = warpN * 32 + nb * 8 + t * 2;
            const float bs0 = s_b[oc], bs1 = s_b[oc + 1];
            const size_t base =
                (((size_t)b * C_OUT + oc) * H_OUT + (p0 + pr)) * W_OUT + q0;
            if (qq0 < qcnt) {
                out[base + qq0]                          = acc[mb][nb][0] + bs0;
                out[base + (size_t)H_OUT * W_OUT + qq0]  = acc[mb][nb][1] + bs1;
            }
            if (qq0 + 8 < qcnt) {
                out[base + qq0 + 8]                         = acc[mb][nb][2] + bs0;
                out[base + (size_t)H_OUT * W_OUT + qq0 + 8] = acc[mb][nb][3] + bs1;
            }
        }
    }
}

extern "C" void kernel_launch(void* const* d_in, const int* in_sizes, int n_in,
                              void* d_out, int out_size) {
    const float* img    = nullptr;
    const float* depth  = nullptr;
    const float* weight = nullptr;
    const float* bias   = nullptr;

    for (int i = 0; i < n_in; i++) {
        switch (in_sizes[i]) {
            case 4 * C_IN * H_IN * W_IN: img    = (const float*)d_in[i]; break;
            case 4 * 1 * H_IN * W_IN:    depth  = (const float*)d_in[i]; break;
            case C_OUT * C_IN * 9:       weight = (const float*)d_in[i]; break;
            case C_OUT:                  bias   = (const float*)d_in[i]; break;
            default: break;
        }
    }

    cudaFuncSetAttribute(depthconv_mma,
                         cudaFuncAttributeMaxDynamicSharedMemorySize, SMEM_TOTAL);

    prep_w<<<(72 * 8 * 32 + 255) / 256, 256>>>(weight);
    depthconv_mma<<<NTILES, NTHREADS, SMEM_TOTAL>>>(img, depth, bias, (float*)d_out);
}

// round 7
// speedup vs baseline: 4.6636x; 1.0607x over previous
#include <cuda_runtime.h>
#include <math.h>

typedef unsigned int u32;

#define ALPHA   8.3f
#define C_IN    64
#define C_OUT   64
#define H_IN    256
#define W_IN    256
#define H_OUT   254
#define W_OUT   254

#define NTHREADS 128
#define TILES_PER_BATCH (127 * 4)   // 127 p-pairs x 4 q-tiles of 64
#define NTILES   (4 * TILES_PER_BATCH)

// ---- smem layout (bytes) ----
#define OFF_BIAS 0                       // 64 f            = 256
#define OFF_D    256                     // 4 x 66 f        = 1056
#define OFF_DW   1312                    // 9 x 128 f       = 4608
#define OFF_IMG  5920                    // 64 x 264 f      = 67584
#define SMEM_TOTAL 73504

__device__ __forceinline__ u32 to_tf32(float x) {
    u32 u;
    asm("cvt.rn.tf32.f32 %0, %1;" : "=r"(u) : "f"(x));
    return u;
}

// mma.sync m16n8k8 tf32: D(16x8,f32) += A(16x8,tf32) * B(8x8,tf32)
#define MMA_TF32(d, a, b0, b1)                                              \
    asm volatile(                                                           \
        "mma.sync.aligned.m16n8k8.row.col.f32.tf32.tf32.f32 "               \
        "{%0,%1,%2,%3}, {%4,%5,%6,%7}, {%8,%9}, {%0,%1,%2,%3};"             \
        : "+f"((d)[0]), "+f"((d)[1]), "+f"((d)[2]), "+f"((d)[3])            \
        : "r"((a)[0]), "r"((a)[1]), "r"((a)[2]), "r"((a)[3]),               \
          "r"(b0), "r"(b1))

// W pre-packed: [kc(72)][nbp(4)][lane(32)] float4.
// kc = kl*8 + cs. For nb pair (2*nbp, 2*nbp+1):
//   .x/.y = B regs (k=t, k=t+4) of nb_even, .z/.w = same of nb_odd,
// where lane holds B col g = lane>>2 (oc = nb*8+g), k-row t = lane&3,
// channel c = cs*8 + t (and +4 in the second reg).
__device__ __align__(16) float4 g_wfragP[72 * 4 * 32];

__global__ void prep_w(const float* __restrict__ w) {
    int idx = blockIdx.x * blockDim.x + threadIdx.x;
    if (idx >= 72 * 4 * 32) return;
    int lane = idx & 31;
    int nbp  = (idx >> 5) & 3;
    int kc   = idx >> 7;
    int kl = kc >> 3, cs = kc & 7;
    int g = lane >> 2, t = lane & 3;
    int c0 = cs * 8 + t;
    int oce = (2 * nbp)     * 8 + g;
    int oco = (2 * nbp + 1) * 8 + g;
    float4 v;
    v.x = __uint_as_float(to_tf32(w[(oce * C_IN + c0)     * 9 + kl]));
    v.y = __uint_as_float(to_tf32(w[(oce * C_IN + c0 + 4) * 9 + kl]));
    v.z = __uint_as_float(to_tf32(w[(oco * C_IN + c0)     * 9 + kl]));
    v.w = __uint_as_float(to_tf32(w[(oco * C_IN + c0 + 4) * 9 + kl]));
    g_wfragP[idx] = v;
}

__global__ __launch_bounds__(NTHREADS, 3)
void depthconv_mma(const float* __restrict__ img,
                   const float* __restrict__ depth,
                   const float* __restrict__ bias,
                   float* __restrict__ out) {
    extern __shared__ char smem[];
    float*  s_b   = (float*) (smem + OFF_BIAS);
    float*  s_d   = (float*) (smem + OFF_D);
    float*  s_dw  = (float*) (smem + OFF_DW);
    float*  s_img = (float*) (smem + OFF_IMG);

    const int tid   = threadIdx.x;
    const int lane  = tid & 31;
    const int wid   = tid >> 5;          // 4 warps, all N; 32 M rows each
    const int g     = lane >> 2;
    const int t     = lane & 3;
    const int pr    = wid >> 1;          // output row within p-pair
    const int qb0   = (wid & 1) * 32;    // q base of this warp's 32-wide strip

    const int tIdx = blockIdx.x;
    const int b  = tIdx / TILES_PER_BATCH;
    const int r  = tIdx - b * TILES_PER_BATCH;
    const int p0 = (r >> 2) << 1;        // 0..252
    const int q0 = (r & 3) << 6;
    const int qcnt = min(64, W_OUT - q0);

    // ---- stage bias + depth halo (4 x 66) ----
    if (tid < C_OUT) s_b[tid] = bias[tid];
    for (int i = tid; i < 264; i += NTHREADS) {
        int rr = i / 66, cc = i - rr * 66;
        s_d[i] = depth[(size_t)b * H_IN * W_IN + (p0 + rr) * W_IN +
                       min(q0 + cc, W_IN - 1)];
    }
    // ---- stage img: 64 ch x 4 rows x 66 q ----
    {
        const float* ip = img + (size_t)b * C_IN * H_IN * W_IN;
        for (int c = wid; c < C_IN; c += 4) {
            const float* row0 = ip + ((size_t)c * H_IN + p0) * W_IN;
            float* sd = s_img + c * 264;
#pragma unroll
            for (int rr = 0; rr < 4; rr++) {
#pragma unroll
                for (int cc = lane; cc < 66; cc += 32)
                    sd[rr * 66 + cc] = row0[rr * W_IN + min(q0 + cc, W_IN - 1)];
            }
        }
    }
    __syncthreads();
    // ---- dw[kl][m] (channel-independent) ----
    for (int i = tid; i < 1152; i += NTHREADS) {
        int kl = i >> 7, m = i & 127;
        int mpr = m >> 6, qq = m & 63;
        int k = kl / 3, l = kl - k * 3;
        float cen = s_d[(mpr + 1) * 66 + qq + 1];
        s_dw[i] = __expf(-ALPHA * fabsf(s_d[(mpr + k) * 66 + qq + l] - cen));
    }
    __syncthreads();

    float acc[2][8][4];
#pragma unroll
    for (int mb = 0; mb < 2; mb++)
#pragma unroll
        for (int nb = 0; nb < 8; nb++)
#pragma unroll
            for (int rr = 0; rr < 4; rr++) acc[mb][nb][rr] = 0.f;

    // ---- K loop: (k,l) outer (not unrolled: keep I$ in L0), cs inner x8 ----
    const float4* wlane = g_wfragP + lane;
    for (int k = 0; k < 3; k++) {
#pragma unroll 1
        for (int l = 0; l < 3; l++) {
            const int kl = k * 3 + l;
            const float* dwp = s_dw + kl * 128 + pr * 64 + qb0;
            const float dw00 = dwp[g];
            const float dw01 = dwp[g + 8];
            const float dw10 = dwp[16 + g];
            const float dw11 = dwp[16 + g + 8];
            const float* pbase = s_img + (pr + k) * 66 + l + qb0;

#pragma unroll
            for (int cs = 0; cs < 8; cs++) {
                const int kc = kl * 8 + cs;
                const float4* wf = wlane + (size_t)kc * 128;
                float4 bq0 = __ldg(wf);
                float4 bq1 = __ldg(wf + 32);
                float4 bq2 = __ldg(wf + 64);
                float4 bq3 = __ldg(wf + 96);

                const float* pc0 = pbase + (cs * 8 + t) * 264;   // channel c0
                const float* pc1 = pc0 + 4 * 264;                // channel c0+4

                u32 A0[4], A1[4];
                A0[0] = to_tf32(pc0[g]          * dw00);
                A0[1] = to_tf32(pc0[g + 8]      * dw01);
                A0[2] = to_tf32(pc1[g]          * dw00);
                A0[3] = to_tf32(pc1[g + 8]      * dw01);
                A1[0] = to_tf32(pc0[16 + g]     * dw10);
                A1[1] = to_tf32(pc0[16 + g + 8] * dw11);
                A1[2] = to_tf32(pc1[16 + g]     * dw10);
                A1[3] = to_tf32(pc1[16 + g + 8] * dw11);

                MMA_TF32(acc[0][0], A0, __float_as_uint(bq0.x), __float_as_uint(bq0.y));
                MMA_TF32(acc[1][0], A1, __float_as_uint(bq0.x), __float_as_uint(bq0.y));
                MMA_TF32(acc[0][1], A0, __float_as_uint(bq0.z), __float_as_uint(bq0.w));
                MMA_TF32(acc[1][1], A1, __float_as_uint(bq0.z), __float_as_uint(bq0.w));
                MMA_TF32(acc[0][2], A0, __float_as_uint(bq1.x), __float_as_uint(bq1.y));
                MMA_TF32(acc[1][2], A1, __float_as_uint(bq1.x), __float_as_uint(bq1.y));
                MMA_TF32(acc[0][3], A0, __float_as_uint(bq1.z), __float_as_uint(bq1.w));
                MMA_TF32(acc[1][3], A1, __float_as_uint(bq1.z), __float_as_uint(bq1.w));
                MMA_TF32(acc[0][4], A0, __float_as_uint(bq2.x), __float_as_uint(bq2.y));
                MMA_TF32(acc[1][4], A1, __float_as_uint(bq2.x), __float_as_uint(bq2.y));
                MMA_TF32(acc[0][5], A0, __float_as_uint(bq2.z), __float_as_uint(bq2.w));
                MMA_TF32(acc[1][5], A1, __float_as_uint(bq2.z), __float_as_uint(bq2.w));
                MMA_TF32(acc[0][6], A0, __float_as_uint(bq3.x), __float_as_uint(bq3.y));
                MMA_TF32(acc[1][6], A1, __float_as_uint(bq3.x), __float_as_uint(bq3.y));
                MMA_TF32(acc[0][7], A0, __float_as_uint(bq3.z), __float_as_uint(bq3.w));
                MMA_TF32(acc[1][7], A1, __float_as_uint(bq3.z), __float_as_uint(bq3.w));
            }
        }
    }

    // ---- epilogue: bias + store ----
#pragma unroll
    for (int mb = 0; mb < 2; mb++) {
        const int qq0 = qb0 + mb * 16 + g;
#pragma unroll
        for (int nb = 0; nb < 8; nb++) {
            const int oc = nb * 8 + t * 2;
            const float bs0 = s_b[oc], bs1 = s_b[oc + 1];
            const size_t base =
                (((size_t)b * C_OUT + oc) * H_OUT + (p0 + pr)) * W_OUT + q0;
            if (qq0 < qcnt) {
                out[base + qq0]                          = acc[mb][nb][0] + bs0;
                out[base + (size_t)H_OUT * W_OUT + qq0]  = acc[mb][nb][1] + bs1;
            }
            if (qq0 + 8 < qcnt) {
                out[base + qq0 + 8]                         = acc[mb][nb][2] + bs0;
                out[base + (size_t)H_OUT * W_OUT + qq0 + 8] = acc[mb][nb][3] + bs1;
            }
        }
    }
}

extern "C" void kernel_launch(void* const* d_in, const int* in_sizes, int n_in,
                              void* d_out, int out_size) {
    const float* img    = nullptr;
    const float* depth  = nullptr;
    const float* weight = nullptr;
    const float* bias   = nullptr;

    for (int i = 0; i < n_in; i++) {
        switch (in_sizes[i]) {
            case 4 * C_IN * H_IN * W_IN: img    = (const float*)d_in[i]; break;
            case 4 * 1 * H_IN * W_IN:    depth  = (const float*)d_in[i]; break;
            case C_OUT * C_IN * 9:       weight = (const float*)d_in[i]; break;
            case C_OUT:                  bias   = (const float*)d_in[i]; break;
            default: break;
        }
    }

    cudaFuncSetAttribute(depthconv_mma,
                         cudaFuncAttributeMaxDynamicSharedMemorySize, SMEM_TOTAL);

    prep_w<<<(72 * 4 * 32 + 255) / 256, 256>>>(weight);
    depthconv_mma<<<NTILES, NTHREADS, SMEM_TOTAL>>>(img, depth, bias, (float*)d_out);
}

// round 8
// speedup vs baseline: 5.4734x; 1.1736x over previous
#include <cuda_runtime.h>
#include <cuda_fp16.h>
#include <math.h>

typedef unsigned int u32;

#define ALPHA   8.3f
#define C_IN    64
#define C_OUT   64
#define H_IN    256
#define W_IN    256
#define H_OUT   254
#define W_OUT   254

#define NTHREADS 128
#define TILES_PER_BATCH (127 * 4)   // 127 p-pairs x 4 q-tiles of 64
#define NTILES   (4 * TILES_PER_BATCH)

#define CSTR     268                 // img channel stride (floats), bank-safe for 2t/2t+1

// ---- smem layout (bytes) ----
#define OFF_BIAS 0                   // 64 f             = 256
#define OFF_D    256                 // 4 x 66 f         = 1056
#define OFF_DW   1312                // 9 x 128 f        = 4608
#define OFF_IMG  5920                // 64 x 268 f       = 68608
#define SMEM_TOTAL 74528

__device__ __forceinline__ u32 packh2(float lo, float hi) {
    u32 r;
    asm("cvt.rn.f16x2.f32 %0, %1, %2;" : "=r"(r) : "f"(hi), "f"(lo));
    return r;
}

// mma.sync m16n8k16 fp16: D(16x8,f32) += A(16x16,f16) * B(16x8,f16)
#define MMA_F16(d, a, b0, b1)                                               \
    asm volatile(                                                           \
        "mma.sync.aligned.m16n8k16.row.col.f32.f16.f16.f32 "                \
        "{%0,%1,%2,%3}, {%4,%5,%6,%7}, {%8,%9}, {%0,%1,%2,%3};"             \
        : "+f"((d)[0]), "+f"((d)[1]), "+f"((d)[2]), "+f"((d)[3])            \
        : "r"((a)[0]), "r"((a)[1]), "r"((a)[2]), "r"((a)[3]),               \
          "r"(b0), "r"(b1))

// W pre-packed fp16 B-fragments: [kc16(36)][j(4)][lane(32)] uint4.
// kc16 = kl*4 + cq (cq = 16-channel chunk). For nb pair (2j, 2j+1):
//   .x = b0(nb_even) = {W[oce][c+2t] lo, W[oce][c+2t+1] hi}
//   .y = b1(nb_even) = {W[oce][c+2t+8],  W[oce][c+2t+9]}
//   .z/.w = same for nb_odd;  oc = nb*8 + g,  c = cq*16.
__device__ __align__(16) uint4 g_wh[36 * 4 * 32];

__global__ void prep_w(const float* __restrict__ w) {
    int idx = blockIdx.x * blockDim.x + threadIdx.x;
    if (idx >= 36 * 4 * 32) return;
    int lane = idx & 31;
    int j    = (idx >> 5) & 3;
    int kc16 = idx >> 7;
    int kl = kc16 >> 2, cq = kc16 & 3;
    int g = lane >> 2, t = lane & 3;
    int c0 = cq * 16 + 2 * t;
    int oce = (2 * j) * 8 + g;
    int oco = oce + 8;
    uint4 v;
    v.x = packh2(w[(oce * C_IN + c0)     * 9 + kl], w[(oce * C_IN + c0 + 1) * 9 + kl]);
    v.y = packh2(w[(oce * C_IN + c0 + 8) * 9 + kl], w[(oce * C_IN + c0 + 9) * 9 + kl]);
    v.z = packh2(w[(oco * C_IN + c0)     * 9 + kl], w[(oco * C_IN + c0 + 1) * 9 + kl]);
    v.w = packh2(w[(oco * C_IN + c0 + 8) * 9 + kl], w[(oco * C_IN + c0 + 9) * 9 + kl]);
    g_wh[idx] = v;
}

__global__ __launch_bounds__(NTHREADS, 3)
void depthconv_mma(const float* __restrict__ img,
                   const float* __restrict__ depth,
                   const float* __restrict__ bias,
                   float* __restrict__ out) {
    extern __shared__ char smem[];
    float*  s_b   = (float*) (smem + OFF_BIAS);
    float*  s_d   = (float*) (smem + OFF_D);
    float*  s_dw  = (float*) (smem + OFF_DW);
    float*  s_img = (float*) (smem + OFF_IMG);

    const int tid   = threadIdx.x;
    const int lane  = tid & 31;
    const int wid   = tid >> 5;          // 4 warps: each 32 M-pixels x 64 oc
    const int g     = lane >> 2;
    const int t     = lane & 3;
    const int pr    = wid >> 1;          // output row within p-pair
    const int qb0   = (wid & 1) * 32;    // q base of this warp's strip

    const int tIdx = blockIdx.x;
    const int b  = tIdx / TILES_PER_BATCH;
    const int r  = tIdx - b * TILES_PER_BATCH;
    const int p0 = (r >> 2) << 1;        // 0..252
    const int q0 = (r & 3) << 6;
    const int qcnt = min(64, W_OUT - q0);

    // ---- stage bias + depth halo (4 x 66) ----
    if (tid < C_OUT) s_b[tid] = bias[tid];
    for (int i = tid; i < 264; i += NTHREADS) {
        int rr = i / 66, cc = i - rr * 66;
        s_d[i] = depth[(size_t)b * H_IN * W_IN + (p0 + rr) * W_IN +
                       min(q0 + cc, W_IN - 1)];
    }
    // ---- stage img: 64 ch x 4 rows x 66 q ----
    {
        const float* ip = img + (size_t)b * C_IN * H_IN * W_IN;
        for (int c = wid; c < C_IN; c += 4) {
            const float* row0 = ip + ((size_t)c * H_IN + p0) * W_IN;
            float* sd = s_img + c * CSTR;
#pragma unroll
            for (int rr = 0; rr < 4; rr++) {
#pragma unroll
                for (int cc = lane; cc < 66; cc += 32)
                    sd[rr * 66 + cc] = row0[rr * W_IN + min(q0 + cc, W_IN - 1)];
            }
        }
    }
    __syncthreads();
    // ---- dw[kl][m] (channel-independent) ----
    for (int i = tid; i < 1152; i += NTHREADS) {
        int kl = i >> 7, m = i & 127;
        int mpr = m >> 6, qq = m & 63;
        int k = kl / 3, l = kl - k * 3;
        float cen = s_d[(mpr + 1) * 66 + qq + 1];
        s_dw[i] = __expf(-ALPHA * fabsf(s_d[(mpr + k) * 66 + qq + l] - cen));
    }
    __syncthreads();

    float acc[2][8][4];
#pragma unroll
    for (int mb = 0; mb < 2; mb++)
#pragma unroll
        for (int nb = 0; nb < 8; nb++)
#pragma unroll
            for (int rr = 0; rr < 4; rr++) acc[mb][nb][rr] = 0.f;

    // ---- K loop: kl outer (not unrolled), cq inner x4 (16 channels each) ----
    const uint4* wlane = g_wh + lane;
    for (int k = 0; k < 3; k++) {
#pragma unroll 1
        for (int l = 0; l < 3; l++) {
            const int kl = k * 3 + l;
            const float* dwp = s_dw + kl * 128 + pr * 64 + qb0;
            const float dw00 = dwp[g];
            const float dw01 = dwp[g + 8];
            const float dw10 = dwp[16 + g];
            const float dw11 = dwp[16 + g + 8];
            const float* pbase = s_img + (pr + k) * 66 + l + qb0;

#pragma unroll
            for (int cq = 0; cq < 4; cq++) {
                const int kc16 = kl * 4 + cq;
                const uint4* wf = wlane + (size_t)kc16 * 128;
                uint4 bq0 = __ldg(wf);
                uint4 bq1 = __ldg(wf + 32);
                uint4 bq2 = __ldg(wf + 64);
                uint4 bq3 = __ldg(wf + 96);

                const float* p0c = pbase + (cq * 16 + 2 * t) * CSTR; // ch even
                const float* p1c = p0c + CSTR;                        // ch odd
                const float* p8c = p0c + 8 * CSTR;                    // ch even+8
                const float* p9c = p8c + CSTR;                        // ch odd+8

                u32 A0[4], A1[4];
                A0[0] = packh2(p0c[g]      * dw00, p1c[g]      * dw00);
                A0[1] = packh2(p0c[g + 8]  * dw01, p1c[g + 8]  * dw01);
                A0[2] = packh2(p8c[g]      * dw00, p9c[g]      * dw00);
                A0[3] = packh2(p8c[g + 8]  * dw01, p9c[g + 8]  * dw01);
                A1[0] = packh2(p0c[16 + g]     * dw10, p1c[16 + g]     * dw10);
                A1[1] = packh2(p0c[16 + g + 8] * dw11, p1c[16 + g + 8] * dw11);
                A1[2] = packh2(p8c[16 + g]     * dw10, p9c[16 + g]     * dw10);
                A1[3] = packh2(p8c[16 + g + 8] * dw11, p9c[16 + g + 8] * dw11);

                MMA_F16(acc[0][0], A0, bq0.x, bq0.y);
                MMA_F16(acc[1][0], A1, bq0.x, bq0.y);
                MMA_F16(acc[0][1], A0, bq0.z, bq0.w);
                MMA_F16(acc[1][1], A1, bq0.z, bq0.w);
                MMA_F16(acc[0][2], A0, bq1.x, bq1.y);
                MMA_F16(acc[1][2], A1, bq1.x, bq1.y);
                MMA_F16(acc[0][3], A0, bq1.z, bq1.w);
                MMA_F16(acc[1][3], A1, bq1.z, bq1.w);
                MMA_F16(acc[0][4], A0, bq2.x, bq2.y);
                MMA_F16(acc[1][4], A1, bq2.x, bq2.y);
                MMA_F16(acc[0][5], A0, bq2.z, bq2.w);
                MMA_F16(acc[1][5], A1, bq2.z, bq2.w);
                MMA_F16(acc[0][6], A0, bq3.x, bq3.y);
                MMA_F16(acc[1][6], A1, bq3.x, bq3.y);
                MMA_F16(acc[0][7], A0, bq3.z, bq3.w);
                MMA_F16(acc[1][7], A1, bq3.z, bq3.w);
            }
        }
    }

    // ---- epilogue: bias + store ----
    // C frag: c0,c1 = (row g, cols 2t,2t+1); c2,c3 = (row g+8, same cols)
#pragma unroll
    for (int mb = 0; mb < 2; mb++) {
        const int qq0 = qb0 + mb * 16 + g;
#pragma unroll
        for (int nb = 0; nb < 8; nb++) {
            const int oc = nb * 8 + t * 2;
            const float bs0 = s_b[oc], bs1 = s_b[oc + 1];
            const size_t base =
                (((size_t)b * C_OUT + oc) * H_OUT + (p0 + pr)) * W_OUT + q0;
            if (qq0 < qcnt) {
                out[base + qq0]                          = acc[mb][nb][0] + bs0;
                out[base + (size_t)H_OUT * W_OUT + qq0]  = acc[mb][nb][1] + bs1;
            }
            if (qq0 + 8 < qcnt) {
                out[base + qq0 + 8]                         = acc[mb][nb][2] + bs0;
                out[base + (size_t)H_OUT * W_OUT + qq0 + 8] = acc[mb][nb][3] + bs1;
            }
        }
    }
}

extern "C" void kernel_launch(void* const* d_in, const int* in_sizes, int n_in,
                              void* d_out, int out_size) {
    const float* img    = nullptr;
    const float* depth  = nullptr;
    const float* weight = nullptr;
    const float* bias   = nullptr;

    for (int i = 0; i < n_in; i++) {
        switch (in_sizes[i]) {
            case 4 * C_IN * H_IN * W_IN: img    = (const float*)d_in[i]; break;
            case 4 * 1 * H_IN * W_IN:    depth  = (const float*)d_in[i]; break;
            case C_OUT * C_IN * 9:       weight = (const float*)d_in[i]; break;
            case C_OUT:                  bias   = (const float*)d_in[i]; break;
            default: break;
        }
    }

    cudaFuncSetAttribute(depthconv_mma,
                         cudaFuncAttributeMaxDynamicSharedMemorySize, SMEM_TOTAL);

    prep_w<<<(36 * 4 * 32 + 255) / 256, 256>>>(weight);
    depthconv_mma<<<NTILES, NTHREADS, SMEM_TOTAL>>>(img, depth, bias, (float*)d_out);
}

// round 9
// speedup vs baseline: 5.9072x; 1.0793x over previous
#include <cuda_runtime.h>
#include <cuda_fp16.h>
#include <math.h>

typedef unsigned int u32;

#define ALPHA   8.3f
#define C_IN    64
#define C_OUT   64
#define H_IN    256
#define W_IN    256
#define H_OUT   254
#define W_OUT   254

#define NTHREADS 128
#define TILES_PER_BATCH (127 * 4)   // 127 p-pairs x 4 q-tiles of 64
#define NTILES   (4 * TILES_PER_BATCH)

#define PIXN     264                 // 4 rows x 66 cols
// ---- smem layout (bytes) ----
#define OFF_BIAS 0                   // 64 f              = 256
#define OFF_D    256                 // 4 x 66 f          = 1056
#define OFF_DW   1312                // 9 x 128 f         = 4608
#define OFF_IMGH 5920                // 32 cpair x 264 u32 = 33792
#define SMEM_TOTAL 39712

__device__ __forceinline__ u32 packh2(float lo, float hi) {
    u32 r;
    asm("cvt.rn.f16x2.f32 %0, %1, %2;" : "=r"(r) : "f"(hi), "f"(lo));
    return r;
}
__device__ __forceinline__ u32 hmul2(u32 a, u32 b) {
    u32 r;
    asm("mul.rn.f16x2 %0, %1, %2;" : "=r"(r) : "r"(a), "r"(b));
    return r;
}

// mma.sync m16n8k16 fp16: D(16x8,f32) += A(16x16,f16) * B(16x8,f16)
#define MMA_F16(d, a, b0, b1)                                               \
    asm volatile(                                                           \
        "mma.sync.aligned.m16n8k16.row.col.f32.f16.f16.f32 "                \
        "{%0,%1,%2,%3}, {%4,%5,%6,%7}, {%8,%9}, {%0,%1,%2,%3};"             \
        : "+f"((d)[0]), "+f"((d)[1]), "+f"((d)[2]), "+f"((d)[3])            \
        : "r"((a)[0]), "r"((a)[1]), "r"((a)[2]), "r"((a)[3]),               \
          "r"(b0), "r"(b1))

// W pre-packed fp16 B-fragments: [kc16(36)][j(4)][lane(32)] uint4.
// kc16 = kl*4 + cq. For nb pair (2j, 2j+1):
//   .x = b0(nb_even) = {W[oce][c+2t], W[oce][c+2t+1]}
//   .y = b1(nb_even) = {W[oce][c+2t+8], W[oce][c+2t+9]}
//   .z/.w = same for nb_odd;  oc = nb*8 + g,  c = cq*16.
__device__ __align__(16) uint4 g_wh[36 * 4 * 32];

__global__ void prep_w(const float* __restrict__ w) {
    int idx = blockIdx.x * blockDim.x + threadIdx.x;
    if (idx >= 36 * 4 * 32) return;
    int lane = idx & 31;
    int j    = (idx >> 5) & 3;
    int kc16 = idx >> 7;
    int kl = kc16 >> 2, cq = kc16 & 3;
    int g = lane >> 2, t = lane & 3;
    int c0 = cq * 16 + 2 * t;
    int oce = (2 * j) * 8 + g;
    int oco = oce + 8;
    uint4 v;
    v.x = packh2(w[(oce * C_IN + c0)     * 9 + kl], w[(oce * C_IN + c0 + 1) * 9 + kl]);
    v.y = packh2(w[(oce * C_IN + c0 + 8) * 9 + kl], w[(oce * C_IN + c0 + 9) * 9 + kl]);
    v.z = packh2(w[(oco * C_IN + c0)     * 9 + kl], w[(oco * C_IN + c0 + 1) * 9 + kl]);
    v.w = packh2(w[(oco * C_IN + c0 + 8) * 9 + kl], w[(oco * C_IN + c0 + 9) * 9 + kl]);
    g_wh[idx] = v;
}

__global__ __launch_bounds__(NTHREADS, 4)
void depthconv_mma(const float* __restrict__ img,
                   const float* __restrict__ depth,
                   const float* __restrict__ bias,
                   float* __restrict__ out) {
    extern __shared__ char smem[];
    float* s_b    = (float*)(smem + OFF_BIAS);
    float* s_d    = (float*)(smem + OFF_D);
    float* s_dw   = (float*)(smem + OFF_DW);
    u32*   s_imgh = (u32*)  (smem + OFF_IMGH);   // [cpair(32)][pix(264)]

    const int tid  = threadIdx.x;
    const int lane = tid & 31;
    const int wid  = tid >> 5;          // 4 warps: each 32 M-pixels x 64 oc
    const int g    = lane >> 2;
    const int t    = lane & 3;
    const int pr   = wid >> 1;          // output row within p-pair
    const int qb0  = (wid & 1) * 32;    // q base of this warp's strip

    const int tIdx = blockIdx.x;
    const int b  = tIdx / TILES_PER_BATCH;
    const int r  = tIdx - b * TILES_PER_BATCH;
    const int p0 = (r >> 2) << 1;       // 0..252
    const int q0 = (r & 3) << 6;
    const int qcnt = min(64, W_OUT - q0);

    // ---- stage bias + depth halo (4 x 66) ----
    if (tid < C_OUT) s_b[tid] = bias[tid];
    for (int i = tid; i < 264; i += NTHREADS) {
        int rr = i / 66, cc = i - rr * 66;
        s_d[i] = depth[(size_t)b * H_IN * W_IN + (p0 + rr) * W_IN +
                       min(q0 + cc, W_IN - 1)];
    }
    // ---- stage img as fp16x2 channel pairs: s_imgh[cpair][pix] ----
    {
        const float* ip = img + (size_t)b * C_IN * H_IN * W_IN;
        for (int i = tid; i < 32 * PIXN; i += NTHREADS) {
            int cp  = i / PIXN;
            int pix = i - cp * PIXN;
            int rr  = pix / 66, cc = pix - rr * 66;
            size_t go = ((size_t)(2 * cp) * H_IN + (p0 + rr)) * W_IN +
                        min(q0 + cc, W_IN - 1);
            float f0 = ip[go];
            float f1 = ip[go + (size_t)H_IN * W_IN];
            s_imgh[cp * PIXN + pix] = packh2(f0, f1);
        }
    }
    __syncthreads();
    // ---- dw[kl][m] (channel-independent) ----
    for (int i = tid; i < 1152; i += NTHREADS) {
        int kl = i >> 7, m = i & 127;
        int mpr = m >> 6, qq = m & 63;
        int k = kl / 3, l = kl - k * 3;
        float cen = s_d[(mpr + 1) * 66 + qq + 1];
        s_dw[i] = __expf(-ALPHA * fabsf(s_d[(mpr + k) * 66 + qq + l] - cen));
    }
    __syncthreads();

    float acc[2][8][4];
#pragma unroll
    for (int mb = 0; mb < 2; mb++)
#pragma unroll
        for (int nb = 0; nb < 8; nb++)
#pragma unroll
            for (int rr = 0; rr < 4; rr++) acc[mb][nb][rr] = 0.f;

    // ---- K loop: kl outer (not unrolled), cq inner x4 (16 channels each) ----
    const uint4* wlane = g_wh + lane;
    for (int k = 0; k < 3; k++) {
#pragma unroll 1
        for (int l = 0; l < 3; l++) {
            const int kl = k * 3 + l;
            const float* dwp = s_dw + kl * 128 + pr * 64 + qb0;
            const u32 dwh00 = packh2(dwp[g],          dwp[g]);
            const u32 dwh01 = packh2(dwp[g + 8],      dwp[g + 8]);
            const u32 dwh10 = packh2(dwp[16 + g],     dwp[16 + g]);
            const u32 dwh11 = packh2(dwp[16 + g + 8], dwp[16 + g + 8]);
            const int pixbase = (pr + k) * 66 + l + qb0;

#pragma unroll
            for (int cq = 0; cq < 4; cq++) {
                const int kc16 = kl * 4 + cq;
                const uint4* wf = wlane + (size_t)kc16 * 128;
                uint4 bq0 = __ldg(wf);
                uint4 bq1 = __ldg(wf + 32);
                uint4 bq2 = __ldg(wf + 64);
                uint4 bq3 = __ldg(wf + 96);

                // cpair row: channels {2t,2t+1} of this 16-ch chunk
                const u32* pc  = s_imgh + (cq * 8 + t) * PIXN + pixbase;
                const u32* pc4 = pc + 4 * PIXN;    // channels +8

                u32 A0[4], A1[4];
                A0[0] = hmul2(pc [g],      dwh00);
                A0[1] = hmul2(pc [g + 8],  dwh01);
                A0[2] = hmul2(pc4[g],      dwh00);
                A0[3] = hmul2(pc4[g + 8],  dwh01);
                A1[0] = hmul2(pc [16 + g],     dwh10);
                A1[1] = hmul2(pc [16 + g + 8], dwh11);
                A1[2] = hmul2(pc4[16 + g],     dwh10);
                A1[3] = hmul2(pc4[16 + g + 8], dwh11);

                MMA_F16(acc[0][0], A0, bq0.x, bq0.y);
                MMA_F16(acc[1][0], A1, bq0.x, bq0.y);
                MMA_F16(acc[0][1], A0, bq0.z, bq0.w);
                MMA_F16(acc[1][1], A1, bq0.z, bq0.w);
                MMA_F16(acc[0][2], A0, bq1.x, bq1.y);
                MMA_F16(acc[1][2], A1, bq1.x, bq1.y);
                MMA_F16(acc[0][3], A0, bq1.z, bq1.w);
                MMA_F16(acc[1][3], A1, bq1.z, bq1.w);
                MMA_F16(acc[0][4], A0, bq2.x, bq2.y);
                MMA_F16(acc[1][4], A1, bq2.x, bq2.y);
                MMA_F16(acc[0][5], A0, bq2.z, bq2.w);
                MMA_F16(acc[1][5], A1, bq2.z, bq2.w);
                MMA_F16(acc[0][6], A0, bq3.x, bq3.y);
                MMA_F16(acc[1][6], A1, bq3.x, bq3.y);
                MMA_F16(acc[0][7], A0, bq3.z, bq3.w);
                MMA_F16(acc[1][7], A1, bq3.z, bq3.w);
            }
        }
    }

    // ---- epilogue: bias + store ----
#pragma unroll
    for (int mb = 0; mb < 2; mb++) {
        const int qq0 = qb0 + mb * 16 + g;
#pragma unroll
        for (int nb = 0; nb < 8; nb++) {
            const int oc = nb * 8 + t * 2;
            const float bs0 = s_b[oc], bs1 = s_b[oc + 1];
            const size_t base =
                (((size_t)b * C_OUT + oc) * H_OUT + (p0 + pr)) * W_OUT + q0;
            if (qq0 < qcnt) {
                out[base + qq0]                          = acc[mb][nb][0] + bs0;
                out[base + (size_t)H_OUT * W_OUT + qq0]  = acc[mb][nb][1] + bs1;
            }
            if (qq0 + 8 < qcnt) {
                out[base + qq0 + 8]                         = acc[mb][nb][2] + bs0;
                out[base + (size_t)H_OUT * W_OUT + qq0 + 8] = acc[mb][nb][3] + bs1;
            }
        }
    }
}

extern "C" void kernel_launch(void* const* d_in, const int* in_sizes, int n_in,
                              void* d_out, int out_size) {
    const float* img    = nullptr;
    const float* depth  = nullptr;
    const float* weight = nullptr;
    const float* bias   = nullptr;

    for (int i = 0; i < n_in; i++) {
        switch (in_sizes[i]) {
            case 4 * C_IN * H_IN * W_IN: img    = (const float*)d_in[i]; break;
            case 4 * 1 * H_IN * W_IN:    depth  = (const float*)d_in[i]; break;
            case C_OUT * C_IN * 9:       weight = (const float*)d_in[i]; break;
            case C_OUT:                  bias   = (const float*)d_in[i]; break;
            default: break;
        }
    }

    cudaFuncSetAttribute(depthconv_mma,
                         cudaFuncAttributeMaxDynamicSharedMemorySize, SMEM_TOTAL);

    prep_w<<<(36 * 4 * 32 + 255) / 256, 256>>>(weight);
    depthconv_mma<<<NTILES, NTHREADS, SMEM_TOTAL>>>(img, depth, bias, (float*)d_out);
}